// round 2
// baseline (speedup 1.0000x reference)
#include <cuda_runtime.h>
#include <math.h>

#define EPSF 1e-8f
#define RCUT 4.8f
#define NBC 64
#define NN 20
#define HID 64

// ---- dynamic shared layout (floats) ----
// weights region (shared by all 4 lanes)
static constexpr int OW0   = 0;      // W0 padded [15][65] = 975 -> pad 976
static constexpr int OW1   = 976;    // W1 padded [64][65] = 4160
static constexpr int OW2   = 5136;   // 64
static constexpr int OB0   = 5200;   // 64
static constexpr int OB1   = 5264;   // 64
static constexpr int OMISC = 5328;   // [0]=b2, [1..3]=a_j=f1^2+eps, [4..6]=p_j=f2^2+eps ; pad 16
static constexpr int WFL   = 5344;

// per-lane region (offsets relative to lane base)
static constexpr int LR    = 0;      // R[64]
static constexpr int LSEL  = 64;     // int sel[20] (stored via cast), pad to 84
static constexpr int LNDN  = 84;     // ndn[20][3] = 60
static constexpr int LNOR  = 144;    // nor[20][9] = 180
static constexpr int LNEWR = 324;    // 20
static constexpr int LFCR  = 344;    // 20
static constexpr int LSO   = 364;    // orientation 9, pad 12
static constexpr int LFEAT = 376;    // featT [15][20] = 300  (row stride 20, float4-aligned)
static constexpr int LH1   = 676;    // h1T [64][20] = 1280
static constexpr int LH2   = 1956;   // h2T [64][20] = 1280
static constexpr int LGF   = 3236;   // gfeat [20][16] = 320
static constexpr int LGZ   = 3556;   // 20
static constexpr int LDN   = 3576;   // 20
static constexpr int LENC  = 3596;   // 20
static constexpr int LPN   = 3616;   // 20
static constexpr int LGO   = 3636;   // 9, pad 12
static constexpr int LSC   = 3648;   // [0]=S, [1]=F, pad 4
static constexpr int LANE_FLOATS = 3652;

static constexpr int SMEM_FLOATS = WFL + 4 * LANE_FLOATS;   // 19952 floats = 79808 B

__global__ __launch_bounds__(256, 2)
void ep_kernel(const float* __restrict__ dr,
               const float* __restrict__ orientation,
               const float* __restrict__ n_or,
               const float* __restrict__ W0, const float* __restrict__ b0,
               const float* __restrict__ W1, const float* __restrict__ b1,
               const float* __restrict__ W2, const float* __restrict__ b2,
               const float* __restrict__ f1, const float* __restrict__ f2,
               float* __restrict__ out, int B)
{
    extern __shared__ float sm[];
    const int tid = threadIdx.x;

    // ---- stage weights into padded shared ----
    for (int idx = tid; idx < 15 * 64; idx += 256) {
        int i = idx >> 6, j = idx & 63;
        sm[OW0 + i * 65 + j] = W0[idx];
    }
    for (int idx = tid; idx < 64 * 64; idx += 256) {
        int k = idx >> 6, j = idx & 63;
        sm[OW1 + k * 65 + j] = W1[idx];
    }
    for (int idx = tid; idx < 64; idx += 256) {
        sm[OW2 + idx] = W2[idx];
        sm[OB0 + idx] = b0[idx];
        sm[OB1 + idx] = b1[idx];
    }
    if (tid == 0) {
        sm[OMISC + 0] = b2[0];
        #pragma unroll
        for (int j = 0; j < 3; j++) {
            float a = f1[j]; sm[OMISC + 1 + j] = a * a + EPSF;
            float p = f2[j]; sm[OMISC + 4 + j] = p * p + EPSF;
        }
    }

    const int lane = tid >> 6;          // 0..3
    const int t    = tid & 63;          // 0..63
    const int batch0 = blockIdx.x * 4 + lane;
    const bool wr = batch0 < B;
    const int batch = wr ? batch0 : 0;
    float* L = sm + WFL + lane * LANE_FLOATS;
    int* sel = (int*)(L + LSEL);

    // ---- phase 1: radii + orientation stage ----
    {
        const float* d = dr + (size_t)batch * NBC * 3 + t * 3;
        float x = d[0] + EPSF, y = d[1] + EPSF, z = d[2] + EPSF;
        L[LR + t] = sqrtf(x * x + y * y + z * z);
        if (t < 9) L[LSO + t] = orientation[(size_t)batch * 9 + t];
    }
    __syncthreads();

    // ---- phase 2: stable rank (matches stable argsort) ----
    {
        float Rt = L[LR + t];
        int rank = 0;
        #pragma unroll 8
        for (int u = 0; u < NBC; u++) {
            float Ru = L[LR + u];
            rank += (Ru < Rt) || (Ru == Rt && u < t);
        }
        if (rank < NN) sel[rank] = t;
    }
    __syncthreads();

    // ---- phase 3: gather selected neighbors ----
    if (t < NN) {
        int s = sel[t];
        float Rv = L[LR + s];
        L[LNEWR + t] = Rv;
        const float* d = dr + (size_t)batch * NBC * 3 + s * 3;
        float inv = 1.0f / Rv;
        L[LNDN + t * 3 + 0] = (d[0] + EPSF) * inv;
        L[LNDN + t * 3 + 1] = (d[1] + EPSF) * inv;
        L[LNDN + t * 3 + 2] = (d[2] + EPSF) * inv;
        L[LFCR + t] = (Rv > RCUT) ? 0.0f : (0.5f * cospif(Rv * (1.0f / RCUT)) + 0.5f);
        const float* np_ = n_or + ((size_t)batch * NBC + s) * 9;
        #pragma unroll
        for (int e = 0; e < 9; e++) L[LNOR + t * 9 + e] = np_[e];
    }
    __syncthreads();

    // ---- phase 4: featT[i][n] (i feature index 0..14, n neighbor) ----
    for (int p = t; p < NN * 15; p += 64) {
        int n = p / 15, i = p - n * 15;
        const float* nd = L + LNDN + n * 3;
        const float* NO = L + LNOR + n * 9;
        const float* O  = L + LSO;
        float v;
        if (i < 3) {                                     // dr_o[h=i] = sum_k ndn[k]*O[k,i]
            v = nd[0] * O[0 * 3 + i] + nd[1] * O[1 * 3 + i] + nd[2] * O[2 * 3 + i];
        } else if (i < 6) {                              // dr_no[h] = sum_k ndn[k]*N[k,h]
            int h = i - 3;
            v = nd[0] * NO[0 * 3 + h] + nd[1] * NO[1 * 3 + h] + nd[2] * NO[2 * 3 + h];
        } else {                                         // o_no[l,m] = sum_h O[h,l]*N[h,m]
            int l = (i - 6) / 3, m = (i - 6) % 3;
            v = O[0 * 3 + l] * NO[0 * 3 + m] + O[1 * 3 + l] * NO[1 * 3 + m] + O[2 * 3 + l] * NO[2 * 3 + m];
        }
        L[LFEAT + i * NN + n] = v;
    }
    __syncthreads();

    // ---- phase 5: h1 = tanh(feat @ W0 + b0), stored transposed [j][n] ----
    {
        float acc[NN];
        float bb = sm[OB0 + t];
        #pragma unroll
        for (int n = 0; n < NN; n++) acc[n] = bb;
        #pragma unroll
        for (int i = 0; i < 15; i++) {
            float w = sm[OW0 + i * 65 + t];
            const float4* fr = (const float4*)(L + LFEAT + i * NN);
            #pragma unroll
            for (int q = 0; q < 5; q++) {
                float4 f = fr[q];
                acc[4 * q + 0] += f.x * w;
                acc[4 * q + 1] += f.y * w;
                acc[4 * q + 2] += f.z * w;
                acc[4 * q + 3] += f.w * w;
            }
        }
        #pragma unroll
        for (int n = 0; n < NN; n++) L[LH1 + t * NN + n] = tanhf(acc[n]);
    }
    __syncthreads();

    // ---- phase 6: h2 = tanh(h1 @ W1 + b1), transposed ----
    {
        float acc[NN];
        float bb = sm[OB1 + t];
        #pragma unroll
        for (int n = 0; n < NN; n++) acc[n] = bb;
        #pragma unroll 4
        for (int k = 0; k < HID; k++) {
            float w = sm[OW1 + k * 65 + t];
            const float4* fr = (const float4*)(L + LH1 + k * NN);
            #pragma unroll
            for (int q = 0; q < 5; q++) {
                float4 f = fr[q];
                acc[4 * q + 0] += f.x * w;
                acc[4 * q + 1] += f.y * w;
                acc[4 * q + 2] += f.z * w;
                acc[4 * q + 3] += f.w * w;
            }
        }
        #pragma unroll
        for (int n = 0; n < NN; n++) L[LH2 + t * NN + n] = tanhf(acc[n]);
    }
    __syncthreads();

    // ---- phase 7: z, enc, power-law prior pieces (per neighbor) ----
    if (t < NN) {
        float z = sm[OMISC + 0];
        #pragma unroll 8
        for (int j = 0; j < HID; j++) z += L[LH2 + j * NN + t] * sm[OW2 + j];
        float enc = tanhf(z);
        float e = enc * enc + EPSF;
        float Rm = L[LNEWR + t] - e;
        float P = 0.f, Dsum = 0.f;
        #pragma unroll
        for (int j = 0; j < 3; j++) {
            float a = sm[OMISC + 1 + j], p = sm[OMISC + 4 + j];
            float u = a * Rm;
            float tt = exp2f(-p * log2f(u));     // (a*(R-e))^(-p)
            P += tt;
            Dsum += p * tt;
        }
        L[LPN + t]  = P;
        L[LDN + t]  = Dsum / Rm;                 // dE/de_n / F
        L[LENC + t] = enc;
    }
    __syncthreads();
    if (t == 0) {
        float S = 0.f, F = 0.f;
        #pragma unroll
        for (int n = 0; n < NN; n++) { S += L[LPN + n]; F += L[LFCR + n]; }
        L[LSC + 0] = S;
        L[LSC + 1] = F;
    }
    __syncthreads();
    if (t < NN) {
        float F = L[LSC + 1];
        float enc = L[LENC + t];
        L[LGZ + t] = F * L[LDN + t] * 2.f * enc * (1.f - enc * enc);
    }
    __syncthreads();

    // ---- phase 8: g_a2 overwrites h2T ----
    {
        float w2 = sm[OW2 + t];
        #pragma unroll
        for (int n = 0; n < NN; n++) {
            float h2v = L[LH2 + t * NN + n];
            L[LH2 + t * NN + n] = L[LGZ + n] * w2 * (1.f - h2v * h2v);
        }
    }
    __syncthreads();

    // ---- phase 9: g_h1 = g_a2 @ W1^T ; g_a1 overwrites h1T ----
    {
        float acc[NN];
        #pragma unroll
        for (int n = 0; n < NN; n++) acc[n] = 0.f;
        #pragma unroll 4
        for (int j = 0; j < HID; j++) {
            float w = sm[OW1 + t * 65 + j];
            const float4* fr = (const float4*)(L + LH2 + j * NN);
            #pragma unroll
            for (int q = 0; q < 5; q++) {
                float4 f = fr[q];
                acc[4 * q + 0] += f.x * w;
                acc[4 * q + 1] += f.y * w;
                acc[4 * q + 2] += f.z * w;
                acc[4 * q + 3] += f.w * w;
            }
        }
        #pragma unroll
        for (int n = 0; n < NN; n++) {
            float h1v = L[LH1 + t * NN + n];
            L[LH1 + t * NN + n] = acc[n] * (1.f - h1v * h1v);
        }
    }
    __syncthreads();

    // ---- phase 10: g_feat[n][i] = sum_k g_a1[k][n] * W0[i][k] ----
    for (int p = t; p < NN * 15; p += 64) {
        int n = p / 15, i = p - n * 15;
        float s2 = 0.f;
        #pragma unroll 8
        for (int k = 0; k < HID; k++) s2 += L[LH1 + k * NN + n] * sm[OW0 + i * 65 + k];
        L[LGF + n * 16 + i] = s2;
    }
    __syncthreads();

    // ---- phase 11: force, gO, energy ----
    if (t < 3) {
        float f = 0.f;
        const float* O = L + LSO;
        for (int n = 0; n < NN; n++) {
            const float* g  = L + LGF + n * 16;
            const float* NO = L + LNOR + n * 9;
            f += g[0] * O[t * 3 + 0] + g[1] * O[t * 3 + 1] + g[2] * O[t * 3 + 2];
            f += g[3] * NO[t * 3 + 0] + g[4] * NO[t * 3 + 1] + g[5] * NO[t * 3 + 2];
        }
        if (wr) out[(size_t)batch * 3 + t] = f;
    }
    if (t >= 4 && t < 13) {
        int a = (t - 4) / 3, bb = (t - 4) % 3;
        float g2 = 0.f;
        for (int n = 0; n < NN; n++) {
            const float* g  = L + LGF + n * 16;
            const float* NO = L + LNOR + n * 9;
            g2 += L[LNDN + n * 3 + a] * g[bb];
            g2 += g[6 + 3 * bb + 0] * NO[a * 3 + 0]
                + g[6 + 3 * bb + 1] * NO[a * 3 + 1]
                + g[6 + 3 * bb + 2] * NO[a * 3 + 2];
        }
        L[LGO + a * 3 + bb] = g2;
    }
    if (t < NN && wr) {
        out[(size_t)6 * B + (size_t)batch * NN + t] = L[LSC + 0] * L[LFCR + t];
    }
    __syncthreads();
    if (t == 0 && wr) {
        const float* gO = L + LGO;
        const float* O  = L + LSO;
        float tx = 0.f, ty = 0.f, tz = 0.f;
        #pragma unroll
        for (int c = 0; c < 3; c++) {
            float u0 = gO[0 * 3 + c], u1 = gO[1 * 3 + c], u2 = gO[2 * 3 + c];
            float v0 = O[0 * 3 + c],  v1 = O[1 * 3 + c],  v2 = O[2 * 3 + c];
            tx += u1 * v2 - u2 * v1;
            ty += u2 * v0 - u0 * v2;
            tz += u0 * v1 - u1 * v0;
        }
        out[(size_t)3 * B + (size_t)batch * 3 + 0] = tx;
        out[(size_t)3 * B + (size_t)batch * 3 + 1] = ty;
        out[(size_t)3 * B + (size_t)batch * 3 + 2] = tz;
    }
}

extern "C" void kernel_launch(void* const* d_in, const int* in_sizes, int n_in,
                              void* d_out, int out_size) {
    const float* dr  = (const float*)d_in[0];
    const float* ori = (const float*)d_in[1];
    const float* nor = (const float*)d_in[2];
    const float* W0  = (const float*)d_in[3];
    const float* b0  = (const float*)d_in[4];
    const float* W1  = (const float*)d_in[5];
    const float* b1  = (const float*)d_in[6];
    const float* W2  = (const float*)d_in[7];
    const float* b2  = (const float*)d_in[8];
    const float* f1  = (const float*)d_in[9];
    const float* f2  = (const float*)d_in[10];
    float* out = (float*)d_out;

    int B = in_sizes[0] / (NBC * 3);
    int blocks = (B + 3) / 4;
    size_t shmem = (size_t)SMEM_FLOATS * sizeof(float);
    cudaFuncSetAttribute(ep_kernel, cudaFuncAttributeMaxDynamicSharedMemorySize, (int)shmem);
    ep_kernel<<<blocks, 256, shmem>>>(dr, ori, nor, W0, b0, W1, b1, W2, b2, f1, f2, out, B);
}

// round 4
// speedup vs baseline: 1.2165x; 1.2165x over previous
#include <cuda_runtime.h>
#include <math.h>

#define EPSF 1e-8f
#define NBC 64
#define NN 20
#define TPB 192
#define LPB 12

// weights region (floats)
static constexpr int OW0 = 0, OW1 = 976, OW2 = 5136, OB0 = 5200, OB1 = 5264, OMISC = 5328, WFL = 5344;
// per-lane offsets
static constexpr int LNDN = 0, LNOR = 60, LNEWR = 240, LFCR = 260, LSO = 280, LZ = 292,
    LGZ = 312, LP = 332, LGPRE = 352, LENC = 372, LSC = 392, LGO = 396, LGF = 408,
    LDRW = 728, LRR = 920, LSEL = 984, LFEAT = 1016, LGT = 728, LH1 = 2136, LANE_F = 3568;
static constexpr int SMEM_FLOATS = WFL + LPB * LANE_F;   // 48160 floats = 192640 B

typedef unsigned long long u64;
__device__ __forceinline__ u64 pk2(float a){ u64 r; asm("mov.b64 %0, {%1, %1};":"=l"(r):"f"(a)); return r; }
__device__ __forceinline__ u64 pk(float a,float b){ u64 r; asm("mov.b64 %0, {%1, %2};":"=l"(r):"f"(a),"f"(b)); return r; }
__device__ __forceinline__ void upk(u64 v,float&a,float&b){ asm("mov.b64 {%0, %1}, %2;":"=f"(a),"=f"(b):"l"(v)); }
__device__ __forceinline__ void fma2(u64&c,u64 a,u64 b){ asm("fma.rn.f32x2 %0, %1, %2, %0;":"+l"(c):"l"(a),"l"(b)); }
__device__ __forceinline__ u64 fma2o(u64 a,u64 b,u64 c){ u64 d; asm("fma.rn.f32x2 %0, %1, %2, %3;":"=l"(d):"l"(a),"l"(b),"l"(c)); return d; }
__device__ __forceinline__ u64 mul2(u64 a,u64 b){ u64 d; asm("mul.rn.f32x2 %0, %1, %2;":"=l"(d):"l"(a),"l"(b)); return d; }
__device__ __forceinline__ u64 add2(u64 a,u64 b){ u64 d; asm("add.rn.f32x2 %0, %1, %2;":"=l"(d):"l"(a),"l"(b)); return d; }
__device__ __forceinline__ float ex2a(float x){ float r; asm("ex2.approx.f32 %0, %1;":"=f"(r):"f"(x)); return r; }
__device__ __forceinline__ float lg2a(float x){ float r; asm("lg2.approx.f32 %0, %1;":"=f"(r):"f"(x)); return r; }
__device__ __forceinline__ float rcpa(float x){ float r; asm("rcp.approx.f32 %0, %1;":"=f"(r):"f"(x)); return r; }
__device__ __forceinline__ float tanhfst(float x){
    float e = ex2a(x * 2.885390082f);       // exp(2x)
    return fmaf(-2.0f, rcpa(e + 1.0f), 1.0f);
}
__device__ __forceinline__ u64 tanh2(u64 v){ float a,b; upk(v,a,b); return pk(tanhfst(a), tanhfst(b)); }

__global__ __launch_bounds__(TPB, 1)
void ep_kernel(const float* __restrict__ dr, const float* __restrict__ orientation,
               const float* __restrict__ n_or,
               const float* __restrict__ W0, const float* __restrict__ b0,
               const float* __restrict__ W1, const float* __restrict__ b1,
               const float* __restrict__ W2, const float* __restrict__ b2,
               const float* __restrict__ f1, const float* __restrict__ f2,
               float* __restrict__ out, int B)
{
    extern __shared__ float sm[];
    const int tid = threadIdx.x;
    for (int idx = tid; idx < 960; idx += TPB)  { int i=idx>>6, j=idx&63; sm[OW0+i*65+j]=W0[idx]; }
    for (int idx = tid; idx < 4096; idx += TPB) { int k=idx>>6, j=idx&63; sm[OW1+k*65+j]=W1[idx]; }
    if (tid < 64) { sm[OW2+tid]=W2[tid]; sm[OB0+tid]=b0[tid]; sm[OB1+tid]=b1[tid]; }
    if (tid == 0) {
        sm[OMISC] = b2[0];
        #pragma unroll
        for (int j = 0; j < 3; j++) {
            float a=f1[j]; sm[OMISC+1+j]=a*a+EPSF;
            float p=f2[j]; sm[OMISC+4+j]=p*p+EPSF;
        }
    }
    __syncthreads();

    const int li = tid >> 4, s = tid & 15;
    const int batch0 = blockIdx.x * LPB + li;
    const bool wr = batch0 < B;
    const int batch = wr ? batch0 : 0;
    float* L = sm + WFL + li * LANE_F;
    int* selp = (int*)(L + LSEL);

    // A: stage dr + orientation
    {
        const float4* src = (const float4*)(dr + (size_t)batch * 192);
        float4* dst = (float4*)(L + LDRW);
        dst[s] = src[s]; dst[s+16] = src[s+16]; dst[s+32] = src[s+32];
        if (s < 9) L[LSO+s] = orientation[(size_t)batch*9 + s];
    }
    __syncwarp();
    // B: radii
    #pragma unroll
    for (int c = 0; c < 4; c++) {
        int u = 4*s+c;
        float x=L[LDRW+u*3]+EPSF, y=L[LDRW+u*3+1]+EPSF, z=L[LDRW+u*3+2]+EPSF;
        L[LRR+u] = sqrtf(x*x+y*y+z*z);
    }
    __syncwarp();
    // C: stable rank
    {
        float Ru[4]; int rk[4];
        #pragma unroll
        for (int c=0;c<4;c++){ Ru[c]=L[LRR+4*s+c]; rk[c]=0; }
        const float4* R4 = (const float4*)(L + LRR);
        #pragma unroll 4
        for (int v4=0; v4<16; v4++){
            float4 rv = R4[v4]; int v = 4*v4;
            #pragma unroll
            for (int c=0;c<4;c++){
                int u = 4*s+c;
                rk[c] += (rv.x<Ru[c])||(rv.x==Ru[c]&&v  <u);
                rk[c] += (rv.y<Ru[c])||(rv.y==Ru[c]&&v+1<u);
                rk[c] += (rv.z<Ru[c])||(rv.z==Ru[c]&&v+2<u);
                rk[c] += (rv.w<Ru[c])||(rv.w==Ru[c]&&v+3<u);
            }
        }
        #pragma unroll
        for (int c=0;c<4;c++) if (rk[c] < NN) selp[rk[c]] = 4*s+c;
    }
    __syncwarp();
    // D: gather top-20
    #pragma unroll
    for (int rr = 0; rr < 2; rr++) {
        int n = s + 16*rr;
        if (rr == 0 || s < 4) {
            int u = selp[n];
            float Rv = L[LRR+u];
            L[LNEWR+n] = Rv;
            float inv = 1.0f / Rv;
            L[LNDN+n*3+0] = (L[LDRW+u*3+0]+EPSF)*inv;
            L[LNDN+n*3+1] = (L[LDRW+u*3+1]+EPSF)*inv;
            L[LNDN+n*3+2] = (L[LDRW+u*3+2]+EPSF)*inv;
            L[LFCR+n] = (Rv > 4.8f) ? 0.0f : (0.5f*cospif(Rv*(1.0f/4.8f)) + 0.5f);
            const float* np_ = n_or + ((size_t)batch*NBC + u)*9;
            #pragma unroll
            for (int e = 0; e < 9; e++) L[LNOR+n*9+e] = np_[e];
        }
    }
    __syncwarp();
    // E: features featT[i][n], stride 22
    for (int p = s; p < NN*15; p += 16) {
        int n = p / 15, i = p - n*15;
        const float* nd = L+LNDN+n*3; const float* NO = L+LNOR+n*9; const float* O = L+LSO;
        float v;
        if (i < 3)      v = nd[0]*O[i]   + nd[1]*O[3+i]   + nd[2]*O[6+i];
        else if (i < 6){ int h=i-3; v = nd[0]*NO[h] + nd[1]*NO[3+h] + nd[2]*NO[6+h]; }
        else { int l=(i-6)/3, m=(i-6)%3; v = O[l]*NO[m] + O[3+l]*NO[3+m] + O[6+l]*NO[6+m]; }
        L[LFEAT + i*22 + n] = v;
    }
    __syncwarp();

    u64 acc[40];
    // F: GEMM1 -> h1 (store to smem)
    #pragma unroll
    for (int i=0;i<4;i++){ u64 bb=pk2(sm[OB0+s+16*i]);
        #pragma unroll
        for (int q=0;q<10;q++) acc[i*10+q]=bb; }
    #pragma unroll 5
    for (int k=0;k<15;k++){
        u64 wA=pk2(sm[OW0+k*65+s]),    wB=pk2(sm[OW0+k*65+s+16]);
        u64 wC=pk2(sm[OW0+k*65+s+32]), wD=pk2(sm[OW0+k*65+s+48]);
        const u64* ap=(const u64*)(L+LFEAT+k*22);
        #pragma unroll
        for (int q=0;q<10;q++){ u64 av=ap[q];
            fma2(acc[q],wA,av); fma2(acc[10+q],wB,av);
            fma2(acc[20+q],wC,av); fma2(acc[30+q],wD,av); }
    }
    #pragma unroll
    for (int i=0;i<4;i++){
        u64* hr=(u64*)(L+LH1+(s+16*i)*22);
        #pragma unroll
        for (int q=0;q<10;q++) hr[q]=tanh2(acc[i*10+q]);
    }
    __syncwarp();
    // G: GEMM2 -> h2 (registers only)
    #pragma unroll
    for (int i=0;i<4;i++){ u64 bb=pk2(sm[OB1+s+16*i]);
        #pragma unroll
        for (int q=0;q<10;q++) acc[i*10+q]=bb; }
    #pragma unroll 4
    for (int k=0;k<64;k++){
        u64 wA=pk2(sm[OW1+k*65+s]),    wB=pk2(sm[OW1+k*65+s+16]);
        u64 wC=pk2(sm[OW1+k*65+s+32]), wD=pk2(sm[OW1+k*65+s+48]);
        const u64* ap=(const u64*)(L+LH1+k*22);
        #pragma unroll
        for (int q=0;q<10;q++){ u64 av=ap[q];
            fma2(acc[q],wA,av); fma2(acc[10+q],wB,av);
            fma2(acc[20+q],wC,av); fma2(acc[30+q],wD,av); }
    }
    #pragma unroll
    for (int v=0; v<40; v++) acc[v] = tanh2(acc[v]);

    // H: z reduction, enc, prior, gz, energy
    {
        u64 zp[10];
        #pragma unroll
        for (int q=0;q<10;q++) zp[q]=0ull;
        #pragma unroll
        for (int i=0;i<4;i++){ u64 w2p=pk2(sm[OW2+s+16*i]);
            #pragma unroll
            for (int q=0;q<10;q++) fma2(zp[q], w2p, acc[i*10+q]); }
        #pragma unroll
        for (int m=1;m<16;m<<=1){
            #pragma unroll
            for (int q=0;q<10;q++) zp[q]=add2(zp[q], __shfl_xor_sync(0xffffffffu, zp[q], m));
        }
        if (s==0){ u64 b2p=pk2(sm[OMISC]); u64* zz=(u64*)(L+LZ);
            #pragma unroll
            for (int q=0;q<10;q++) zz[q]=add2(zp[q],b2p); }
    }
    __syncwarp();
    #pragma unroll
    for (int rr=0;rr<2;rr++){
        int n = s + 16*rr;
        if (rr==0 || s<4){
            float enc = tanhfst(L[LZ+n]);
            float e = enc*enc + EPSF;
            float Rm = L[LNEWR+n] - e;
            float P=0.f, D=0.f;
            #pragma unroll
            for (int j=0;j<3;j++){
                float a=sm[OMISC+1+j], p=sm[OMISC+4+j];
                float tt = ex2a(-p * lg2a(a*Rm));
                P += tt; D += p*tt;
            }
            L[LP+n]=P; L[LGPRE+n]=D/Rm; L[LENC+n]=enc;
        }
    }
    __syncwarp();
    if (s==0){
        float S=0.f, F=0.f;
        #pragma unroll
        for (int n=0;n<NN;n++){ S+=L[LP+n]; F+=L[LFCR+n]; }
        L[LSC]=S; L[LSC+1]=F;
    }
    __syncwarp();
    #pragma unroll
    for (int rr=0;rr<2;rr++){
        int n = s + 16*rr;
        if (rr==0 || s<4){
            float enc=L[LENC+n];
            L[LGZ+n] = L[LSC+1]*L[LGPRE+n]*2.f*enc*(1.f-enc*enc);
            if (wr) out[(size_t)6*B + (size_t)batch*NN + n] = L[LSC]*L[LFCR+n];
        }
    }
    __syncwarp();
    // I: ga2 from register h2 -> smem (LGT)
    {
        const u64 SGN = 0x8000000080000000ULL;
        u64 one2 = pk2(1.0f);
        #pragma unroll
        for (int i=0;i<4;i++){
            u64 w2p=pk2(sm[OW2+s+16*i]);
            u64* gr=(u64*)(L+LGT+(s+16*i)*22);
            #pragma unroll
            for (int q=0;q<10;q++){
                u64 h2v=acc[i*10+q];
                u64 d = fma2o(h2v ^ SGN, h2v, one2);
                u64 gzq = *(const u64*)(L+LGZ+2*q);
                gr[q] = mul2(mul2(gzq,w2p), d);
            }
        }
    }
    __syncwarp();
    // J: GEMM3 (gh1 = W1 ga2), then ga1 = gh1*(1-h1^2) overwrites LH1
    #pragma unroll
    for (int v=0; v<40; v++) acc[v]=0ull;
    #pragma unroll 4
    for (int k=0;k<64;k++){
        u64 wA=pk2(sm[OW1+ s      *65+k]), wB=pk2(sm[OW1+(s+16)*65+k]);
        u64 wC=pk2(sm[OW1+(s+32)*65+k]),   wD=pk2(sm[OW1+(s+48)*65+k]);
        const u64* ap=(const u64*)(L+LGT+k*22);
        #pragma unroll
        for (int q=0;q<10;q++){ u64 av=ap[q];
            fma2(acc[q],wA,av); fma2(acc[10+q],wB,av);
            fma2(acc[20+q],wC,av); fma2(acc[30+q],wD,av); }
    }
    {
        const u64 SGN = 0x8000000080000000ULL;
        u64 one2 = pk2(1.0f);
        #pragma unroll
        for (int i=0;i<4;i++){
            u64* hr=(u64*)(L+LH1+(s+16*i)*22);
            #pragma unroll
            for (int q=0;q<10;q++){
                u64 h1v=hr[q];
                u64 d = fma2o(h1v ^ SGN, h1v, one2);
                hr[q] = mul2(acc[i*10+q], d);
            }
        }
    }
    __syncwarp();
    // K: GEMM4 gfeat[n][i] = sum_k ga1[k][n] W0[i][k]
    if (s < 15){
        u64 a4[10];
        #pragma unroll
        for (int q=0;q<10;q++) a4[q]=0ull;
        #pragma unroll 4
        for (int k=0;k<64;k++){
            u64 w=pk2(sm[OW0+s*65+k]);
            const u64* ap=(const u64*)(L+LH1+k*22);
            #pragma unroll
            for (int q=0;q<10;q++) fma2(a4[q],w,ap[q]);
        }
        #pragma unroll
        for (int q=0;q<10;q++){
            float lo,hi; upk(a4[q],lo,hi);
            L[LGF+(2*q)*16+s]=lo; L[LGF+(2*q+1)*16+s]=hi;
        }
    }
    __syncwarp();
    // L: force, gO, torque
    if (s < 3){
        float f=0.f; const float* O=L+LSO;
        for (int n=0;n<NN;n++){
            const float* g=L+LGF+n*16; const float* NO=L+LNOR+n*9;
            f += g[0]*O[s*3]+g[1]*O[s*3+1]+g[2]*O[s*3+2];
            f += g[3]*NO[s*3]+g[4]*NO[s*3+1]+g[5]*NO[s*3+2];
        }
        if (wr) out[(size_t)batch*3+s]=f;
    }
    if (s >= 4 && s < 13){
        int a=(s-4)/3, bb=(s-4)%3; float g2=0.f;
        for (int n=0;n<NN;n++){
            const float* g=L+LGF+n*16; const float* NO=L+LNOR+n*9;
            g2 += L[LNDN+n*3+a]*g[bb];
            g2 += g[6+3*bb+0]*NO[a*3+0]+g[6+3*bb+1]*NO[a*3+1]+g[6+3*bb+2]*NO[a*3+2];
        }
        L[LGO+a*3+bb]=g2;
    }
    __syncwarp();
    if (s==0 && wr){
        const float* gO=L+LGO; const float* O=L+LSO;
        float tx=0.f,ty=0.f,tz=0.f;
        #pragma unroll
        for (int c=0;c<3;c++){
            float u0=gO[c],u1=gO[3+c],u2=gO[6+c];
            float v0=O[c], v1=O[3+c], v2=O[6+c];
            tx += u1*v2-u2*v1; ty += u2*v0-u0*v2; tz += u0*v1-u1*v0;
        }
        out[(size_t)3*B+(size_t)batch*3+0]=tx;
        out[(size_t)3*B+(size_t)batch*3+1]=ty;
        out[(size_t)3*B+(size_t)batch*3+2]=tz;
    }
}

extern "C" void kernel_launch(void* const* d_in, const int* in_sizes, int n_in,
                              void* d_out, int out_size) {
    const float* dr  = (const float*)d_in[0];
    const float* ori = (const float*)d_in[1];
    const float* nor = (const float*)d_in[2];
    const float* W0  = (const float*)d_in[3];
    const float* b0  = (const float*)d_in[4];
    const float* W1  = (const float*)d_in[5];
    const float* b1  = (const float*)d_in[6];
    const float* W2  = (const float*)d_in[7];
    const float* b2  = (const float*)d_in[8];
    const float* f1  = (const float*)d_in[9];
    const float* f2  = (const float*)d_in[10];
    float* out = (float*)d_out;

    int B = in_sizes[0] / (NBC * 3);
    int blocks = (B + LPB - 1) / LPB;
    size_t shmem = (size_t)SMEM_FLOATS * sizeof(float);
    cudaFuncSetAttribute(ep_kernel, cudaFuncAttributeMaxDynamicSharedMemorySize, (int)shmem);
    ep_kernel<<<blocks, TPB, shmem>>>(dr, ori, nor, W0, b0, W1, b1, W2, b2, f1, f2, out, B);
}

// round 5
// speedup vs baseline: 1.3642x; 1.1215x over previous
#include <cuda_runtime.h>
#include <math.h>

#define EPSF 1e-8f
#define NBC 64
#define NN 20
#define LPB 14
#define TPB (LPB*32)

// weights region (floats)
static constexpr int OW0 = 0, OW1 = 976, OW2 = 5136, OB0 = 5200, OB1 = 5264, OMISC = 5328, WFL = 5344;
// per-lane offsets (floats)
static constexpr int LNDN = 0, LNOR = 60, LNEWR = 240, LFCR = 260, LSO = 280, LZ = 292,
    LGZ = 312, LP = 332, LGPRE = 352, LENC = 372, LSC = 392, LGO = 396, LGF = 408,
    LDRW = 728, LRR = 920, LSEL = 984, LFEAT = 1016, LGT = 728, LH1 = 2136, LANE_F = 3568;
static constexpr int SMEM_FLOATS = WFL + LPB * LANE_F;   // 55296 floats = 221184 B

typedef unsigned long long u64;
__device__ __forceinline__ u64 pk2(float a){ u64 r; asm("mov.b64 %0, {%1, %1};":"=l"(r):"f"(a)); return r; }
__device__ __forceinline__ u64 pk(float a,float b){ u64 r; asm("mov.b64 %0, {%1, %2};":"=l"(r):"f"(a),"f"(b)); return r; }
__device__ __forceinline__ void upk(u64 v,float&a,float&b){ asm("mov.b64 {%0, %1}, %2;":"=f"(a),"=f"(b):"l"(v)); }
__device__ __forceinline__ void fma2(u64&c,u64 a,u64 b){ asm("fma.rn.f32x2 %0, %1, %2, %0;":"+l"(c):"l"(a),"l"(b)); }
__device__ __forceinline__ u64 fma2o(u64 a,u64 b,u64 c){ u64 d; asm("fma.rn.f32x2 %0, %1, %2, %3;":"=l"(d):"l"(a),"l"(b),"l"(c)); return d; }
__device__ __forceinline__ u64 mul2(u64 a,u64 b){ u64 d; asm("mul.rn.f32x2 %0, %1, %2;":"=l"(d):"l"(a),"l"(b)); return d; }
__device__ __forceinline__ u64 add2(u64 a,u64 b){ u64 d; asm("add.rn.f32x2 %0, %1, %2;":"=l"(d):"l"(a),"l"(b)); return d; }
__device__ __forceinline__ float ex2a(float x){ float r; asm("ex2.approx.f32 %0, %1;":"=f"(r):"f"(x)); return r; }
__device__ __forceinline__ float lg2a(float x){ float r; asm("lg2.approx.f32 %0, %1;":"=f"(r):"f"(x)); return r; }
__device__ __forceinline__ float rcpa(float x){ float r; asm("rcp.approx.f32 %0, %1;":"=f"(r):"f"(x)); return r; }
__device__ __forceinline__ float tanhfst(float x){
    float e = ex2a(x * 2.885390082f);
    return fmaf(-2.0f, rcpa(e + 1.0f), 1.0f);
}
__device__ __forceinline__ u64 tanh2(u64 v){ float a,b; upk(v,a,b); return pk(tanhfst(a), tanhfst(b)); }

__global__ __launch_bounds__(TPB, 1)
void ep_kernel(const float* __restrict__ dr, const float* __restrict__ orientation,
               const float* __restrict__ n_or,
               const float* __restrict__ W0, const float* __restrict__ b0,
               const float* __restrict__ W1, const float* __restrict__ b1,
               const float* __restrict__ W2, const float* __restrict__ b2,
               const float* __restrict__ f1, const float* __restrict__ f2,
               float* __restrict__ out, int B)
{
    extern __shared__ float sm[];
    const int tid = threadIdx.x;
    for (int idx = tid; idx < 960; idx += TPB)  { int i=idx>>6, j=idx&63; sm[OW0+i*65+j]=W0[idx]; }
    for (int idx = tid; idx < 4096; idx += TPB) { int k=idx>>6, j=idx&63; sm[OW1+k*65+j]=W1[idx]; }
    if (tid < 64) { sm[OW2+tid]=W2[tid]; sm[OB0+tid]=b0[tid]; sm[OB1+tid]=b1[tid]; }
    if (tid == 0) {
        sm[OMISC] = b2[0];
        #pragma unroll
        for (int j = 0; j < 3; j++) {
            float a=f1[j]; sm[OMISC+1+j]=a*a+EPSF;
            float p=f2[j]; sm[OMISC+4+j]=p*p+EPSF;
        }
    }
    __syncthreads();

    const int li = tid >> 5, t = tid & 31;
    const int s = t & 15, half = t >> 4;     // j-column s, n-half
    const int batch0 = blockIdx.x * LPB + li;
    const bool wr = batch0 < B;
    const int batch = wr ? batch0 : 0;
    float* L = sm + WFL + li * LANE_F;
    int* selp = (int*)(L + LSEL);

    // A: stage dr + orientation
    {
        const float4* src = (const float4*)(dr + (size_t)batch * 192);
        float4* dst = (float4*)(L + LDRW);
        dst[t] = src[t];
        if (t < 16) dst[t+32] = src[t+32];
        if (t < 9) L[LSO+t] = orientation[(size_t)batch*9 + t];
    }
    __syncwarp();
    // B: radii (2 per thread)
    #pragma unroll
    for (int c = 0; c < 2; c++) {
        int u = 2*t+c;
        float x=L[LDRW+u*3]+EPSF, y=L[LDRW+u*3+1]+EPSF, z=L[LDRW+u*3+2]+EPSF;
        L[LRR+u] = sqrtf(x*x+y*y+z*z);
    }
    __syncwarp();
    // C: stable rank
    {
        float Ru[2]; int rk[2];
        #pragma unroll
        for (int c=0;c<2;c++){ Ru[c]=L[LRR+2*t+c]; rk[c]=0; }
        const float4* R4 = (const float4*)(L + LRR);
        #pragma unroll 4
        for (int v4=0; v4<16; v4++){
            float4 rv = R4[v4]; int v = 4*v4;
            #pragma unroll
            for (int c=0;c<2;c++){
                int u = 2*t+c;
                rk[c] += (rv.x<Ru[c])||(rv.x==Ru[c]&&v  <u);
                rk[c] += (rv.y<Ru[c])||(rv.y==Ru[c]&&v+1<u);
                rk[c] += (rv.z<Ru[c])||(rv.z==Ru[c]&&v+2<u);
                rk[c] += (rv.w<Ru[c])||(rv.w==Ru[c]&&v+3<u);
            }
        }
        #pragma unroll
        for (int c=0;c<2;c++) if (rk[c] < NN) selp[rk[c]] = 2*t+c;
    }
    __syncwarp();
    // D: gather top-20
    if (t < NN) {
        int u = selp[t];
        float Rv = L[LRR+u];
        L[LNEWR+t] = Rv;
        float inv = 1.0f / Rv;
        L[LNDN+t*3+0] = (L[LDRW+u*3+0]+EPSF)*inv;
        L[LNDN+t*3+1] = (L[LDRW+u*3+1]+EPSF)*inv;
        L[LNDN+t*3+2] = (L[LDRW+u*3+2]+EPSF)*inv;
        L[LFCR+t] = (Rv > 4.8f) ? 0.0f : (0.5f*cospif(Rv*(1.0f/4.8f)) + 0.5f);
        const float* np_ = n_or + ((size_t)batch*NBC + u)*9;
        #pragma unroll
        for (int e = 0; e < 9; e++) L[LNOR+t*9+e] = np_[e];
    }
    __syncwarp();
    // E: features featT[i][n], stride 22
    for (int p = t; p < NN*15; p += 32) {
        int n = p / 15, i = p - n*15;
        const float* nd = L+LNDN+n*3; const float* NO = L+LNOR+n*9; const float* O = L+LSO;
        float v;
        if (i < 3)      v = nd[0]*O[i]   + nd[1]*O[3+i]   + nd[2]*O[6+i];
        else if (i < 6){ int h=i-3; v = nd[0]*NO[h] + nd[1]*NO[3+h] + nd[2]*NO[6+h]; }
        else { int l=(i-6)/3, m=(i-6)%3; v = O[l]*NO[m] + O[3+l]*NO[3+m] + O[6+l]*NO[6+m]; }
        L[LFEAT + i*22 + n] = v;
    }
    __syncwarp();

    u64 acc[20];
    // F: GEMM1 -> h1 (4 j-rows x 10 n per thread)
    #pragma unroll
    for (int i=0;i<4;i++){ u64 bb=pk2(sm[OB0+s+16*i]);
        #pragma unroll
        for (int q=0;q<5;q++) acc[i*5+q]=bb; }
    #pragma unroll 5
    for (int k=0;k<15;k++){
        u64 wA=pk2(sm[OW0+k*65+s]),    wB=pk2(sm[OW0+k*65+s+16]);
        u64 wC=pk2(sm[OW0+k*65+s+32]), wD=pk2(sm[OW0+k*65+s+48]);
        const u64* ap=(const u64*)(L+LFEAT+k*22) + 5*half;
        #pragma unroll
        for (int q=0;q<5;q++){ u64 av=ap[q];
            fma2(acc[q],wA,av); fma2(acc[5+q],wB,av);
            fma2(acc[10+q],wC,av); fma2(acc[15+q],wD,av); }
    }
    #pragma unroll
    for (int i=0;i<4;i++){
        u64* hr=(u64*)(L+LH1+(s+16*i)*22) + 5*half;
        #pragma unroll
        for (int q=0;q<5;q++) hr[q]=tanh2(acc[i*5+q]);
    }
    __syncwarp();
    // G: GEMM2 -> h2 (registers only)
    #pragma unroll
    for (int i=0;i<4;i++){ u64 bb=pk2(sm[OB1+s+16*i]);
        #pragma unroll
        for (int q=0;q<5;q++) acc[i*5+q]=bb; }
    #pragma unroll 8
    for (int k=0;k<64;k++){
        u64 wA=pk2(sm[OW1+k*65+s]),    wB=pk2(sm[OW1+k*65+s+16]);
        u64 wC=pk2(sm[OW1+k*65+s+32]), wD=pk2(sm[OW1+k*65+s+48]);
        const u64* ap=(const u64*)(L+LH1+k*22) + 5*half;
        #pragma unroll
        for (int q=0;q<5;q++){ u64 av=ap[q];
            fma2(acc[q],wA,av); fma2(acc[5+q],wB,av);
            fma2(acc[10+q],wC,av); fma2(acc[15+q],wD,av); }
    }
    #pragma unroll
    for (int v=0; v<20; v++) acc[v] = tanh2(acc[v]);

    // H: z reduction (within each 16-thread half), enc, prior
    {
        u64 zp[5];
        #pragma unroll
        for (int q=0;q<5;q++) zp[q]=0ull;
        #pragma unroll
        for (int i=0;i<4;i++){ u64 w2p=pk2(sm[OW2+s+16*i]);
            #pragma unroll
            for (int q=0;q<5;q++) fma2(zp[q], w2p, acc[i*5+q]); }
        #pragma unroll
        for (int m=1;m<16;m<<=1){
            #pragma unroll
            for (int q=0;q<5;q++) zp[q]=add2(zp[q], __shfl_xor_sync(0xffffffffu, zp[q], m));
        }
        if (s==0){ u64 b2p=pk2(sm[OMISC]); u64* zz=(u64*)(L+LZ) + 5*half;
            #pragma unroll
            for (int q=0;q<5;q++) zz[q]=add2(zp[q],b2p); }
    }
    __syncwarp();
    if (t < NN){
        float enc = tanhfst(L[LZ+t]);
        float e = enc*enc + EPSF;
        float Rm = L[LNEWR+t] - e;
        float P=0.f, D=0.f;
        #pragma unroll
        for (int j=0;j<3;j++){
            float a=sm[OMISC+1+j], p=sm[OMISC+4+j];
            float tt = ex2a(-p * lg2a(a*Rm));
            P += tt; D += p*tt;
        }
        L[LP+t]=P; L[LGPRE+t]=D/Rm; L[LENC+t]=enc;
    }
    __syncwarp();
    if (t==0){
        float S=0.f, F=0.f;
        #pragma unroll
        for (int n=0;n<NN;n++){ S+=L[LP+n]; F+=L[LFCR+n]; }
        L[LSC]=S; L[LSC+1]=F;
    }
    __syncwarp();
    if (t < NN){
        float enc=L[LENC+t];
        L[LGZ+t] = L[LSC+1]*L[LGPRE+t]*2.f*enc*(1.f-enc*enc);
        if (wr) out[(size_t)6*B + (size_t)batch*NN + t] = L[LSC]*L[LFCR+t];
    }
    __syncwarp();
    // I: ga2 from register h2 -> smem (LGT)
    {
        const u64 SGN = 0x8000000080000000ULL;
        u64 one2 = pk2(1.0f);
        #pragma unroll
        for (int i=0;i<4;i++){
            u64 w2p=pk2(sm[OW2+s+16*i]);
            u64* gr=(u64*)(L+LGT+(s+16*i)*22) + 5*half;
            #pragma unroll
            for (int q=0;q<5;q++){
                u64 h2v=acc[i*5+q];
                u64 d = fma2o(h2v ^ SGN, h2v, one2);
                u64 gzq = *(const u64*)(L+LGZ+2*(5*half+q));
                gr[q] = mul2(mul2(gzq,w2p), d);
            }
        }
    }
    __syncwarp();
    // J: GEMM3 (gh1 = W1 ga2), then ga1 = gh1*(1-h1^2) overwrites LH1
    #pragma unroll
    for (int v=0; v<20; v++) acc[v]=0ull;
    #pragma unroll 8
    for (int k=0;k<64;k++){
        u64 wA=pk2(sm[OW1+ s      *65+k]), wB=pk2(sm[OW1+(s+16)*65+k]);
        u64 wC=pk2(sm[OW1+(s+32)*65+k]),   wD=pk2(sm[OW1+(s+48)*65+k]);
        const u64* ap=(const u64*)(L+LGT+k*22) + 5*half;
        #pragma unroll
        for (int q=0;q<5;q++){ u64 av=ap[q];
            fma2(acc[q],wA,av); fma2(acc[5+q],wB,av);
            fma2(acc[10+q],wC,av); fma2(acc[15+q],wD,av); }
    }
    {
        const u64 SGN = 0x8000000080000000ULL;
        u64 one2 = pk2(1.0f);
        #pragma unroll
        for (int i=0;i<4;i++){
            u64* hr=(u64*)(L+LH1+(s+16*i)*22) + 5*half;
            #pragma unroll
            for (int q=0;q<5;q++){
                u64 h1v=hr[q];
                u64 d = fma2o(h1v ^ SGN, h1v, one2);
                hr[q] = mul2(acc[i*5+q], d);
            }
        }
    }
    __syncwarp();
    // K: GEMM4 gfeat[n][i] = sum_k ga1[k][n] W0[i][k]
    if (s < 15){
        u64 a4[5];
        #pragma unroll
        for (int q=0;q<5;q++) a4[q]=0ull;
        #pragma unroll 8
        for (int k=0;k<64;k++){
            u64 w=pk2(sm[OW0+s*65+k]);
            const u64* ap=(const u64*)(L+LH1+k*22) + 5*half;
            #pragma unroll
            for (int q=0;q<5;q++) fma2(a4[q],w,ap[q]);
        }
        #pragma unroll
        for (int q=0;q<5;q++){
            float lo,hi; upk(a4[q],lo,hi);
            int n0 = 10*half + 2*q;
            L[LGF+n0*16+s]=lo; L[LGF+(n0+1)*16+s]=hi;
        }
    }
    __syncwarp();
    // L: force, gO, torque
    if (t < 3){
        float f=0.f; const float* O=L+LSO;
        for (int n=0;n<NN;n++){
            const float* g=L+LGF+n*16; const float* NO=L+LNOR+n*9;
            f += g[0]*O[t*3]+g[1]*O[t*3+1]+g[2]*O[t*3+2];
            f += g[3]*NO[t*3]+g[4]*NO[t*3+1]+g[5]*NO[t*3+2];
        }
        if (wr) out[(size_t)batch*3+t]=f;
    }
    if (t >= 4 && t < 13){
        int a=(t-4)/3, bb=(t-4)%3; float g2=0.f;
        for (int n=0;n<NN;n++){
            const float* g=L+LGF+n*16; const float* NO=L+LNOR+n*9;
            g2 += L[LNDN+n*3+a]*g[bb];
            g2 += g[6+3*bb+0]*NO[a*3+0]+g[6+3*bb+1]*NO[a*3+1]+g[6+3*bb+2]*NO[a*3+2];
        }
        L[LGO+a*3+bb]=g2;
    }
    __syncwarp();
    if (t==0 && wr){
        const float* gO=L+LGO; const float* O=L+LSO;
        float tx=0.f,ty=0.f,tz=0.f;
        #pragma unroll
        for (int c=0;c<3;c++){
            float u0=gO[c],u1=gO[3+c],u2=gO[6+c];
            float v0=O[c], v1=O[3+c], v2=O[6+c];
            tx += u1*v2-u2*v1; ty += u2*v0-u0*v2; tz += u0*v1-u1*v0;
        }
        out[(size_t)3*B+(size_t)batch*3+0]=tx;
        out[(size_t)3*B+(size_t)batch*3+1]=ty;
        out[(size_t)3*B+(size_t)batch*3+2]=tz;
    }
}

extern "C" void kernel_launch(void* const* d_in, const int* in_sizes, int n_in,
                              void* d_out, int out_size) {
    const float* dr  = (const float*)d_in[0];
    const float* ori = (const float*)d_in[1];
    const float* nor = (const float*)d_in[2];
    const float* W0  = (const float*)d_in[3];
    const float* b0  = (const float*)d_in[4];
    const float* W1  = (const float*)d_in[5];
    const float* b1  = (const float*)d_in[6];
    const float* W2  = (const float*)d_in[7];
    const float* b2  = (const float*)d_in[8];
    const float* f1  = (const float*)d_in[9];
    const float* f2  = (const float*)d_in[10];
    float* out = (float*)d_out;

    int B = in_sizes[0] / (NBC * 3);
    int blocks = (B + LPB - 1) / LPB;
    size_t shmem = (size_t)SMEM_FLOATS * sizeof(float);
    cudaFuncSetAttribute(ep_kernel, cudaFuncAttributeMaxDynamicSharedMemorySize, (int)shmem);
    ep_kernel<<<blocks, TPB, shmem>>>(dr, ori, nor, W0, b0, W1, b1, W2, b2, f1, f2, out, B);
}

// round 6
// speedup vs baseline: 1.4882x; 1.0908x over previous
#include <cuda_runtime.h>
#include <math.h>

#define EPSF 1e-8f
#define NBC 64
#define NN 20
#define LPB 16
#define TPB (LPB*32)

// weights region (floats)
static constexpr int OW0 = 0, OW1 = 976, OW2 = 5136, OB0 = 5200, OB1 = 5264, OMISC = 5328, WFL = 5344;
// per-lane offsets (floats); stride-20 tiles
static constexpr int LNDN = 0, LNOR = 60, LNEWR = 240, LFCR = 260, LSO = 280, LZ = 292,
    LGZ = 312, LP = 332, LGPRE = 352, LENC = LZ, LSC = 372, LGO = 374, LGF = 384,
    LDRW = 704, LRR = 896, LSEL = 960, LFEAT = 984, LGT = 704, LH1 = 1984, LANE_F = 3280;
static constexpr int SMEM_FLOATS = WFL + LPB * LANE_F;   // 57824 floats = 231296 B

typedef unsigned long long u64;
__device__ __forceinline__ u64 pk2(float a){ u64 r; asm("mov.b64 %0, {%1, %1};":"=l"(r):"f"(a)); return r; }
__device__ __forceinline__ u64 pk(float a,float b){ u64 r; asm("mov.b64 %0, {%1, %2};":"=l"(r):"f"(a),"f"(b)); return r; }
__device__ __forceinline__ void upk(u64 v,float&a,float&b){ asm("mov.b64 {%0, %1}, %2;":"=f"(a),"=f"(b):"l"(v)); }
__device__ __forceinline__ void fma2(u64&c,u64 a,u64 b){ asm("fma.rn.f32x2 %0, %1, %2, %0;":"+l"(c):"l"(a),"l"(b)); }
__device__ __forceinline__ u64 fma2o(u64 a,u64 b,u64 c){ u64 d; asm("fma.rn.f32x2 %0, %1, %2, %3;":"=l"(d):"l"(a),"l"(b),"l"(c)); return d; }
__device__ __forceinline__ u64 mul2(u64 a,u64 b){ u64 d; asm("mul.rn.f32x2 %0, %1, %2;":"=l"(d):"l"(a),"l"(b)); return d; }
__device__ __forceinline__ u64 add2(u64 a,u64 b){ u64 d; asm("add.rn.f32x2 %0, %1, %2;":"=l"(d):"l"(a),"l"(b)); return d; }
__device__ __forceinline__ float ex2a(float x){ float r; asm("ex2.approx.f32 %0, %1;":"=f"(r):"f"(x)); return r; }
__device__ __forceinline__ float lg2a(float x){ float r; asm("lg2.approx.f32 %0, %1;":"=f"(r):"f"(x)); return r; }
__device__ __forceinline__ float rcpa(float x){ float r; asm("rcp.approx.f32 %0, %1;":"=f"(r):"f"(x)); return r; }
__device__ __forceinline__ float tanhfst(float x){
    float e = ex2a(x * 2.885390082f);
    return fmaf(-2.0f, rcpa(e + 1.0f), 1.0f);
}
__device__ __forceinline__ u64 tanh2(u64 v){ float a,b; upk(v,a,b); return pk(tanhfst(a), tanhfst(b)); }

__global__ __launch_bounds__(TPB, 1)
void ep_kernel(const float* __restrict__ dr, const float* __restrict__ orientation,
               const float* __restrict__ n_or,
               const float* __restrict__ W0, const float* __restrict__ b0,
               const float* __restrict__ W1, const float* __restrict__ b1,
               const float* __restrict__ W2, const float* __restrict__ b2,
               const float* __restrict__ f1, const float* __restrict__ f2,
               float* __restrict__ out, int B)
{
    extern __shared__ float sm[];
    const int tid = threadIdx.x;
    for (int idx = tid; idx < 960; idx += TPB)  { int i=idx>>6, j=idx&63; sm[OW0+i*65+j]=W0[idx]; }
    for (int idx = tid; idx < 4096; idx += TPB) { int k=idx>>6, j=idx&63; sm[OW1+k*65+j]=W1[idx]; }
    if (tid < 64) { sm[OW2+tid]=W2[tid]; sm[OB0+tid]=b0[tid]; sm[OB1+tid]=b1[tid]; }
    if (tid == 0) {
        sm[OMISC] = b2[0];
        #pragma unroll
        for (int j = 0; j < 3; j++) {
            float a=f1[j]; sm[OMISC+1+j]=a*a+EPSF;
            float p=f2[j]; sm[OMISC+4+j]=p*p+EPSF;
        }
    }
    __syncthreads();

    const int li = tid >> 5, t = tid & 31;
    const int s = t & 15, half = t >> 4;
    const int batch0 = blockIdx.x * LPB + li;
    const bool wr = batch0 < B;
    const int batch = wr ? batch0 : 0;
    float* L = sm + WFL + li * LANE_F;
    int* selp = (int*)(L + LSEL);

    // A: stage dr + orientation
    {
        const float4* src = (const float4*)(dr + (size_t)batch * 192);
        float4* dst = (float4*)(L + LDRW);
        dst[t] = src[t];
        if (t < 16) dst[t+32] = src[t+32];
        if (t < 9) L[LSO+t] = orientation[(size_t)batch*9 + t];
    }
    __syncwarp();
    // B: radii
    #pragma unroll
    for (int c = 0; c < 2; c++) {
        int u = 2*t+c;
        float x=L[LDRW+u*3]+EPSF, y=L[LDRW+u*3+1]+EPSF, z=L[LDRW+u*3+2]+EPSF;
        L[LRR+u] = sqrtf(x*x+y*y+z*z);
    }
    __syncwarp();
    // C: stable rank
    {
        float Ru[2]; int rk[2];
        #pragma unroll
        for (int c=0;c<2;c++){ Ru[c]=L[LRR+2*t+c]; rk[c]=0; }
        const float4* R4 = (const float4*)(L + LRR);
        #pragma unroll 4
        for (int v4=0; v4<16; v4++){
            float4 rv = R4[v4]; int v = 4*v4;
            #pragma unroll
            for (int c=0;c<2;c++){
                int u = 2*t+c;
                rk[c] += (rv.x<Ru[c])||(rv.x==Ru[c]&&v  <u);
                rk[c] += (rv.y<Ru[c])||(rv.y==Ru[c]&&v+1<u);
                rk[c] += (rv.z<Ru[c])||(rv.z==Ru[c]&&v+2<u);
                rk[c] += (rv.w<Ru[c])||(rv.w==Ru[c]&&v+3<u);
            }
        }
        #pragma unroll
        for (int c=0;c<2;c++) if (rk[c] < NN) selp[rk[c]] = 2*t+c;
    }
    __syncwarp();
    // D: gather top-20
    if (t < NN) {
        int u = selp[t];
        float Rv = L[LRR+u];
        L[LNEWR+t] = Rv;
        float inv = 1.0f / Rv;
        L[LNDN+t*3+0] = (L[LDRW+u*3+0]+EPSF)*inv;
        L[LNDN+t*3+1] = (L[LDRW+u*3+1]+EPSF)*inv;
        L[LNDN+t*3+2] = (L[LDRW+u*3+2]+EPSF)*inv;
        L[LFCR+t] = (Rv > 4.8f) ? 0.0f : (0.5f*cospif(Rv*(1.0f/4.8f)) + 0.5f);
        const float* np_ = n_or + ((size_t)batch*NBC + u)*9;
        #pragma unroll
        for (int e = 0; e < 9; e++) L[LNOR+t*9+e] = np_[e];
    }
    __syncwarp();
    // E: features featT[i][n], stride 20, div-free index walk
    {
        int n = (t * 0x8889) >> 19;          // t/15 for t<32
        int i = t - n*15;
        #pragma unroll
        for (int it = 0; it < 10; it++) {
            int p = t + 32*it;
            if (p < 300) {
                const float* nd = L+LNDN+n*3; const float* NO = L+LNOR+n*9; const float* O = L+LSO;
                float v;
                if (i < 3)      v = nd[0]*O[i]   + nd[1]*O[3+i]   + nd[2]*O[6+i];
                else if (i < 6){ int h=i-3; v = nd[0]*NO[h] + nd[1]*NO[3+h] + nd[2]*NO[6+h]; }
                else { int l=(i-6)/3, m=(i-6)%3; v = O[l]*NO[m] + O[3+l]*NO[3+m] + O[6+l]*NO[6+m]; }
                L[LFEAT + i*20 + n] = v;
            }
            n += 2; i += 2;
            if (i >= 15) { i -= 15; n += 1; }
        }
    }
    __syncwarp();

    u64 acc[20];
    // F: GEMM1 -> h1
    #pragma unroll
    for (int i=0;i<4;i++){ u64 bb=pk2(sm[OB0+s+16*i]);
        #pragma unroll
        for (int q=0;q<5;q++) acc[i*5+q]=bb; }
    #pragma unroll 5
    for (int k=0;k<15;k++){
        u64 wA=pk2(sm[OW0+k*65+s]),    wB=pk2(sm[OW0+k*65+s+16]);
        u64 wC=pk2(sm[OW0+k*65+s+32]), wD=pk2(sm[OW0+k*65+s+48]);
        const u64* ap=(const u64*)(L+LFEAT+k*20) + 5*half;
        #pragma unroll
        for (int q=0;q<5;q++){ u64 av=ap[q];
            fma2(acc[q],wA,av); fma2(acc[5+q],wB,av);
            fma2(acc[10+q],wC,av); fma2(acc[15+q],wD,av); }
    }
    #pragma unroll
    for (int i=0;i<4;i++){
        u64* hr=(u64*)(L+LH1+(s+16*i)*20) + 5*half;
        #pragma unroll
        for (int q=0;q<5;q++) hr[q]=tanh2(acc[i*5+q]);
    }
    __syncwarp();
    // G: GEMM2 -> h2 (registers only)
    #pragma unroll
    for (int i=0;i<4;i++){ u64 bb=pk2(sm[OB1+s+16*i]);
        #pragma unroll
        for (int q=0;q<5;q++) acc[i*5+q]=bb; }
    #pragma unroll 8
    for (int k=0;k<64;k++){
        u64 wA=pk2(sm[OW1+k*65+s]),    wB=pk2(sm[OW1+k*65+s+16]);
        u64 wC=pk2(sm[OW1+k*65+s+32]), wD=pk2(sm[OW1+k*65+s+48]);
        const u64* ap=(const u64*)(L+LH1+k*20) + 5*half;
        #pragma unroll
        for (int q=0;q<5;q++){ u64 av=ap[q];
            fma2(acc[q],wA,av); fma2(acc[5+q],wB,av);
            fma2(acc[10+q],wC,av); fma2(acc[15+q],wD,av); }
    }
    #pragma unroll
    for (int v=0; v<20; v++) acc[v] = tanh2(acc[v]);

    // H: z reduction, enc, prior
    {
        u64 zp[5];
        #pragma unroll
        for (int q=0;q<5;q++) zp[q]=0ull;
        #pragma unroll
        for (int i=0;i<4;i++){ u64 w2p=pk2(sm[OW2+s+16*i]);
            #pragma unroll
            for (int q=0;q<5;q++) fma2(zp[q], w2p, acc[i*5+q]); }
        #pragma unroll
        for (int m=1;m<16;m<<=1){
            #pragma unroll
            for (int q=0;q<5;q++) zp[q]=add2(zp[q], __shfl_xor_sync(0xffffffffu, zp[q], m));
        }
        if (s==0){ u64 b2p=pk2(sm[OMISC]); u64* zz=(u64*)(L+LZ) + 5*half;
            #pragma unroll
            for (int q=0;q<5;q++) zz[q]=add2(zp[q],b2p); }
    }
    __syncwarp();
    if (t < NN){
        float enc = tanhfst(L[LZ+t]);
        float e = enc*enc + EPSF;
        float Rm = L[LNEWR+t] - e;
        float P=0.f, D=0.f;
        #pragma unroll
        for (int j=0;j<3;j++){
            float a=sm[OMISC+1+j], p=sm[OMISC+4+j];
            float tt = ex2a(-p * lg2a(a*Rm));
            P += tt; D += p*tt;
        }
        L[LP+t]=P; L[LGPRE+t]=D/Rm; L[LENC+t]=enc;
    }
    __syncwarp();
    if (t==0){
        float S=0.f, F=0.f;
        #pragma unroll
        for (int n=0;n<NN;n++){ S+=L[LP+n]; F+=L[LFCR+n]; }
        L[LSC]=S; L[LSC+1]=F;
    }
    __syncwarp();
    if (t < NN){
        float enc=L[LENC+t];
        L[LGZ+t] = L[LSC+1]*L[LGPRE+t]*2.f*enc*(1.f-enc*enc);
        if (wr) out[(size_t)6*B + (size_t)batch*NN + t] = L[LSC]*L[LFCR+t];
    }
    __syncwarp();
    // I: ga2 from register h2 -> smem (LGT)
    {
        const u64 SGN = 0x8000000080000000ULL;
        u64 one2 = pk2(1.0f);
        #pragma unroll
        for (int i=0;i<4;i++){
            u64 w2p=pk2(sm[OW2+s+16*i]);
            u64* gr=(u64*)(L+LGT+(s+16*i)*20) + 5*half;
            #pragma unroll
            for (int q=0;q<5;q++){
                u64 h2v=acc[i*5+q];
                u64 d = fma2o(h2v ^ SGN, h2v, one2);
                u64 gzq = *(const u64*)(L+LGZ+2*(5*half+q));
                gr[q] = mul2(mul2(gzq,w2p), d);
            }
        }
    }
    __syncwarp();
    // J: GEMM3 (gh1 = ga2 @ W1^T), ga1 = gh1*(1-h1^2) overwrites LH1
    #pragma unroll
    for (int v=0; v<20; v++) acc[v]=0ull;
    #pragma unroll 8
    for (int k=0;k<64;k++){
        u64 wA=pk2(sm[OW1+ s      *65+k]), wB=pk2(sm[OW1+(s+16)*65+k]);
        u64 wC=pk2(sm[OW1+(s+32)*65+k]),   wD=pk2(sm[OW1+(s+48)*65+k]);
        const u64* ap=(const u64*)(L+LGT+k*20) + 5*half;
        #pragma unroll
        for (int q=0;q<5;q++){ u64 av=ap[q];
            fma2(acc[q],wA,av); fma2(acc[5+q],wB,av);
            fma2(acc[10+q],wC,av); fma2(acc[15+q],wD,av); }
    }
    {
        const u64 SGN = 0x8000000080000000ULL;
        u64 one2 = pk2(1.0f);
        #pragma unroll
        for (int i=0;i<4;i++){
            u64* hr=(u64*)(L+LH1+(s+16*i)*20) + 5*half;
            #pragma unroll
            for (int q=0;q<5;q++){
                u64 h1v=hr[q];
                u64 d = fma2o(h1v ^ SGN, h1v, one2);
                hr[q] = mul2(acc[i*5+q], d);
            }
        }
    }
    __syncwarp();
    // K: GEMM4 gfeat[n][i] = sum_k ga1[k][n] W0[i][k]
    if (s < 15){
        u64 a4[5];
        #pragma unroll
        for (int q=0;q<5;q++) a4[q]=0ull;
        #pragma unroll 8
        for (int k=0;k<64;k++){
            u64 w=pk2(sm[OW0+s*65+k]);
            const u64* ap=(const u64*)(L+LH1+k*20) + 5*half;
            #pragma unroll
            for (int q=0;q<5;q++) fma2(a4[q],w,ap[q]);
        }
        #pragma unroll
        for (int q=0;q<5;q++){
            float lo,hi; upk(a4[q],lo,hi);
            int n0 = 10*half + 2*q;
            L[LGF+n0*16+s]=lo; L[LGF+(n0+1)*16+s]=hi;
        }
    }
    __syncwarp();
    // L: force, gO, torque
    if (t < 3){
        float f=0.f; const float* O=L+LSO;
        for (int n=0;n<NN;n++){
            const float* g=L+LGF+n*16; const float* NO=L+LNOR+n*9;
            f += g[0]*O[t*3]+g[1]*O[t*3+1]+g[2]*O[t*3+2];
            f += g[3]*NO[t*3]+g[4]*NO[t*3+1]+g[5]*NO[t*3+2];
        }
        if (wr) out[(size_t)batch*3+t]=f;
    }
    if (t >= 4 && t < 13){
        int a=(t-4)/3, bb=(t-4)%3; float g2=0.f;
        for (int n=0;n<NN;n++){
            const float* g=L+LGF+n*16; const float* NO=L+LNOR+n*9;
            g2 += L[LNDN+n*3+a]*g[bb];
            g2 += g[6+3*bb+0]*NO[a*3+0]+g[6+3*bb+1]*NO[a*3+1]+g[6+3*bb+2]*NO[a*3+2];
        }
        L[LGO+a*3+bb]=g2;
    }
    __syncwarp();
    if (t==0 && wr){
        const float* gO=L+LGO; const float* O=L+LSO;
        float tx=0.f,ty=0.f,tz=0.f;
        #pragma unroll
        for (int c=0;c<3;c++){
            float u0=gO[c],u1=gO[3+c],u2=gO[6+c];
            float v0=O[c], v1=O[3+c], v2=O[6+c];
            tx += u1*v2-u2*v1; ty += u2*v0-u0*v2; tz += u0*v1-u1*v0;
        }
        out[(size_t)3*B+(size_t)batch*3+0]=tx;
        out[(size_t)3*B+(size_t)batch*3+1]=ty;
        out[(size_t)3*B+(size_t)batch*3+2]=tz;
    }
}

extern "C" void kernel_launch(void* const* d_in, const int* in_sizes, int n_in,
                              void* d_out, int out_size) {
    const float* dr  = (const float*)d_in[0];
    const float* ori = (const float*)d_in[1];
    const float* nor = (const float*)d_in[2];
    const float* W0  = (const float*)d_in[3];
    const float* b0  = (const float*)d_in[4];
    const float* W1  = (const float*)d_in[5];
    const float* b1  = (const float*)d_in[6];
    const float* W2  = (const float*)d_in[7];
    const float* b2  = (const float*)d_in[8];
    const float* f1  = (const float*)d_in[9];
    const float* f2  = (const float*)d_in[10];
    float* out = (float*)d_out;

    int B = in_sizes[0] / (NBC * 3);
    int blocks = (B + LPB - 1) / LPB;
    size_t shmem = (size_t)SMEM_FLOATS * sizeof(float);
    cudaFuncSetAttribute(ep_kernel, cudaFuncAttributeMaxDynamicSharedMemorySize, (int)shmem);
    ep_kernel<<<blocks, TPB, shmem>>>(dr, ori, nor, W0, b0, W1, b1, W2, b2, f1, f2, out, B);
}

// round 7
// speedup vs baseline: 1.5751x; 1.0584x over previous
#include <cuda_runtime.h>
#include <math.h>

#define EPSF 1e-8f
#define NBC 64
#define NN 20
#define LPB 18
#define TPB (LPB*32)

// weights region (floats)
static constexpr int OW0 = 0, OW1 = 976, OW2 = 5136, OB0 = 5200, OB1 = 5264, OMISC = 5328, WFL = 5336;
// per-lane offsets (floats); mid region (1280 fl) shared by LDRW/LRR/LSEL/LFEAT, LGT, LGF
static constexpr int LNDN = 0, LNOR = 60, LNEWR = 240, LP = 240, LFCR = 260, LGO = 260,
    LSO = 280, LZ = 290, LENC = LZ, LGZ = 310, LGPRE = 330, LSC = 350,
    LDRW = 352, LRR = 544, LSEL = 608, LFEAT = 352, LGT = 352, LGF = 352,
    LH1 = 1632, LANE_F = 2912;
static constexpr int SMEM_FLOATS = WFL + LPB * LANE_F;   // 57752 floats = 231008 B

typedef unsigned long long u64;
__device__ __forceinline__ u64 pk2(float a){ u64 r; asm("mov.b64 %0, {%1, %1};":"=l"(r):"f"(a)); return r; }
__device__ __forceinline__ u64 pk(float a,float b){ u64 r; asm("mov.b64 %0, {%1, %2};":"=l"(r):"f"(a),"f"(b)); return r; }
__device__ __forceinline__ void upk(u64 v,float&a,float&b){ asm("mov.b64 {%0, %1}, %2;":"=f"(a),"=f"(b):"l"(v)); }
__device__ __forceinline__ void fma2(u64&c,u64 a,u64 b){ asm("fma.rn.f32x2 %0, %1, %2, %0;":"+l"(c):"l"(a),"l"(b)); }
__device__ __forceinline__ u64 fma2o(u64 a,u64 b,u64 c){ u64 d; asm("fma.rn.f32x2 %0, %1, %2, %3;":"=l"(d):"l"(a),"l"(b),"l"(c)); return d; }
__device__ __forceinline__ u64 mul2(u64 a,u64 b){ u64 d; asm("mul.rn.f32x2 %0, %1, %2;":"=l"(d):"l"(a),"l"(b)); return d; }
__device__ __forceinline__ u64 add2(u64 a,u64 b){ u64 d; asm("add.rn.f32x2 %0, %1, %2;":"=l"(d):"l"(a),"l"(b)); return d; }
__device__ __forceinline__ float ex2a(float x){ float r; asm("ex2.approx.f32 %0, %1;":"=f"(r):"f"(x)); return r; }
__device__ __forceinline__ float lg2a(float x){ float r; asm("lg2.approx.f32 %0, %1;":"=f"(r):"f"(x)); return r; }
__device__ __forceinline__ float rcpa(float x){ float r; asm("rcp.approx.f32 %0, %1;":"=f"(r):"f"(x)); return r; }
__device__ __forceinline__ float tanhfst(float x){
    float e = ex2a(x * 2.885390082f);
    return fmaf(-2.0f, rcpa(e + 1.0f), 1.0f);
}
__device__ __forceinline__ u64 tanh2(u64 v){ float a,b; upk(v,a,b); return pk(tanhfst(a), tanhfst(b)); }

__global__ __launch_bounds__(TPB, 1)
void ep_kernel(const float* __restrict__ dr, const float* __restrict__ orientation,
               const float* __restrict__ n_or,
               const float* __restrict__ W0, const float* __restrict__ b0,
               const float* __restrict__ W1, const float* __restrict__ b1,
               const float* __restrict__ W2, const float* __restrict__ b2,
               const float* __restrict__ f1, const float* __restrict__ f2,
               float* __restrict__ out, int B)
{
    extern __shared__ float sm[];
    const int tid = threadIdx.x;
    for (int idx = tid; idx < 960; idx += TPB)  { int i=idx>>6, j=idx&63; sm[OW0+i*65+j]=W0[idx]; }
    for (int idx = tid; idx < 4096; idx += TPB) { int k=idx>>6, j=idx&63; sm[OW1+k*65+j]=W1[idx]; }
    if (tid < 64) { sm[OW2+tid]=W2[tid]; sm[OB0+tid]=b0[tid]; sm[OB1+tid]=b1[tid]; }
    if (tid == 0) {
        sm[OMISC] = b2[0];
        #pragma unroll
        for (int j = 0; j < 3; j++) {
            float a=f1[j]; sm[OMISC+1+j]=a*a+EPSF;
            float p=f2[j]; sm[OMISC+4+j]=p*p+EPSF;
        }
    }
    __syncthreads();

    const int li = tid >> 5, t = tid & 31;
    const int s = t & 15, half = t >> 4;
    const int batch0 = blockIdx.x * LPB + li;
    const bool wr = batch0 < B;
    const int batch = wr ? batch0 : 0;
    float* L = sm + WFL + li * LANE_F;
    int* selp = (int*)(L + LSEL);

    // A: stage dr + orientation
    {
        const float4* src = (const float4*)(dr + (size_t)batch * 192);
        float4* dst = (float4*)(L + LDRW);
        dst[t] = src[t];
        if (t < 16) dst[t+32] = src[t+32];
        if (t < 9) L[LSO+t] = orientation[(size_t)batch*9 + t];
    }
    __syncwarp();
    // B: radii
    #pragma unroll
    for (int c = 0; c < 2; c++) {
        int u = 2*t+c;
        float x=L[LDRW+u*3]+EPSF, y=L[LDRW+u*3+1]+EPSF, z=L[LDRW+u*3+2]+EPSF;
        L[LRR+u] = sqrtf(x*x+y*y+z*z);
    }
    __syncwarp();
    // C: stable rank
    {
        float Ru[2]; int rk[2];
        #pragma unroll
        for (int c=0;c<2;c++){ Ru[c]=L[LRR+2*t+c]; rk[c]=0; }
        const float4* R4 = (const float4*)(L + LRR);
        #pragma unroll 4
        for (int v4=0; v4<16; v4++){
            float4 rv = R4[v4]; int v = 4*v4;
            #pragma unroll
            for (int c=0;c<2;c++){
                int u = 2*t+c;
                rk[c] += (rv.x<Ru[c])||(rv.x==Ru[c]&&v  <u);
                rk[c] += (rv.y<Ru[c])||(rv.y==Ru[c]&&v+1<u);
                rk[c] += (rv.z<Ru[c])||(rv.z==Ru[c]&&v+2<u);
                rk[c] += (rv.w<Ru[c])||(rv.w==Ru[c]&&v+3<u);
            }
        }
        #pragma unroll
        for (int c=0;c<2;c++) if (rk[c] < NN) selp[rk[c]] = 2*t+c;
    }
    __syncwarp();
    // D: gather top-20
    if (t < NN) {
        int u = selp[t];
        float Rv = L[LRR+u];
        L[LNEWR+t] = Rv;
        float inv = 1.0f / Rv;
        L[LNDN+t*3+0] = (L[LDRW+u*3+0]+EPSF)*inv;
        L[LNDN+t*3+1] = (L[LDRW+u*3+1]+EPSF)*inv;
        L[LNDN+t*3+2] = (L[LDRW+u*3+2]+EPSF)*inv;
        L[LFCR+t] = (Rv > 4.8f) ? 0.0f : (0.5f*cospif(Rv*(1.0f/4.8f)) + 0.5f);
        const float* np_ = n_or + ((size_t)batch*NBC + u)*9;
        #pragma unroll
        for (int e = 0; e < 9; e++) L[LNOR+t*9+e] = np_[e];
    }
    __syncwarp();
    // E: features featT[i][n], stride 20 (overwrites dead LDRW region)
    {
        int n = (t * 0x8889) >> 19;
        int i = t - n*15;
        #pragma unroll
        for (int it = 0; it < 10; it++) {
            int p = t + 32*it;
            if (p < 300) {
                const float* nd = L+LNDN+n*3; const float* NO = L+LNOR+n*9; const float* O = L+LSO;
                float v;
                if (i < 3)      v = nd[0]*O[i]   + nd[1]*O[3+i]   + nd[2]*O[6+i];
                else if (i < 6){ int h=i-3; v = nd[0]*NO[h] + nd[1]*NO[3+h] + nd[2]*NO[6+h]; }
                else { int l=(i-6)/3, m=(i-6)%3; v = O[l]*NO[m] + O[3+l]*NO[3+m] + O[6+l]*NO[6+m]; }
                L[LFEAT + i*20 + n] = v;
            }
            n += 2; i += 2;
            if (i >= 15) { i -= 15; n += 1; }
        }
    }
    __syncwarp();

    u64 acc[20];
    // F: GEMM1 -> h1
    #pragma unroll
    for (int i=0;i<4;i++){ u64 bb=pk2(sm[OB0+s+16*i]);
        #pragma unroll
        for (int q=0;q<5;q++) acc[i*5+q]=bb; }
    #pragma unroll 5
    for (int k=0;k<15;k++){
        u64 wA=pk2(sm[OW0+k*65+s]),    wB=pk2(sm[OW0+k*65+s+16]);
        u64 wC=pk2(sm[OW0+k*65+s+32]), wD=pk2(sm[OW0+k*65+s+48]);
        const u64* ap=(const u64*)(L+LFEAT+k*20) + 5*half;
        #pragma unroll
        for (int q=0;q<5;q++){ u64 av=ap[q];
            fma2(acc[q],wA,av); fma2(acc[5+q],wB,av);
            fma2(acc[10+q],wC,av); fma2(acc[15+q],wD,av); }
    }
    #pragma unroll
    for (int i=0;i<4;i++){
        u64* hr=(u64*)(L+LH1+(s+16*i)*20) + 5*half;
        #pragma unroll
        for (int q=0;q<5;q++) hr[q]=tanh2(acc[i*5+q]);
    }
    __syncwarp();
    // G: GEMM2 -> h2 (registers only)
    #pragma unroll
    for (int i=0;i<4;i++){ u64 bb=pk2(sm[OB1+s+16*i]);
        #pragma unroll
        for (int q=0;q<5;q++) acc[i*5+q]=bb; }
    #pragma unroll 8
    for (int k=0;k<64;k++){
        u64 wA=pk2(sm[OW1+k*65+s]),    wB=pk2(sm[OW1+k*65+s+16]);
        u64 wC=pk2(sm[OW1+k*65+s+32]), wD=pk2(sm[OW1+k*65+s+48]);
        const u64* ap=(const u64*)(L+LH1+k*20) + 5*half;
        #pragma unroll
        for (int q=0;q<5;q++){ u64 av=ap[q];
            fma2(acc[q],wA,av); fma2(acc[5+q],wB,av);
            fma2(acc[10+q],wC,av); fma2(acc[15+q],wD,av); }
    }
    #pragma unroll
    for (int v=0; v<20; v++) acc[v] = tanh2(acc[v]);

    // H: z reduction, enc, prior
    {
        u64 zp[5];
        #pragma unroll
        for (int q=0;q<5;q++) zp[q]=0ull;
        #pragma unroll
        for (int i=0;i<4;i++){ u64 w2p=pk2(sm[OW2+s+16*i]);
            #pragma unroll
            for (int q=0;q<5;q++) fma2(zp[q], w2p, acc[i*5+q]); }
        #pragma unroll
        for (int m=1;m<16;m<<=1){
            #pragma unroll
            for (int q=0;q<5;q++) zp[q]=add2(zp[q], __shfl_xor_sync(0xffffffffu, zp[q], m));
        }
        if (s==0){ u64 b2p=pk2(sm[OMISC]); u64* zz=(u64*)(L+LZ) + 5*half;
            #pragma unroll
            for (int q=0;q<5;q++) zz[q]=add2(zp[q],b2p); }
    }
    __syncwarp();
    if (t < NN){
        float enc = tanhfst(L[LZ+t]);
        float e = enc*enc + EPSF;
        float Rm = L[LNEWR+t] - e;        // read NEWR, then overwrite (LP aliases)
        float P=0.f, D=0.f;
        #pragma unroll
        for (int j=0;j<3;j++){
            float a=sm[OMISC+1+j], p=sm[OMISC+4+j];
            float tt = ex2a(-p * lg2a(a*Rm));
            P += tt; D += p*tt;
        }
        L[LP+t]=P; L[LGPRE+t]=D/Rm; L[LENC+t]=enc;
    }
    __syncwarp();
    if (t==0){
        float S=0.f, F=0.f;
        #pragma unroll
        for (int n=0;n<NN;n++){ S+=L[LP+n]; F+=L[LFCR+n]; }
        L[LSC]=S; L[LSC+1]=F;
    }
    __syncwarp();
    if (t < NN){
        float enc=L[LENC+t];
        L[LGZ+t] = L[LSC+1]*L[LGPRE+t]*2.f*enc*(1.f-enc*enc);
        if (wr) out[(size_t)6*B + (size_t)batch*NN + t] = L[LSC]*L[LFCR+t];
    }
    __syncwarp();
    // I: ga2 from register h2 -> smem (LGT, over dead feat region)
    {
        const u64 SGN = 0x8000000080000000ULL;
        u64 one2 = pk2(1.0f);
        #pragma unroll
        for (int i=0;i<4;i++){
            u64 w2p=pk2(sm[OW2+s+16*i]);
            u64* gr=(u64*)(L+LGT+(s+16*i)*20) + 5*half;
            #pragma unroll
            for (int q=0;q<5;q++){
                u64 h2v=acc[i*5+q];
                u64 d = fma2o(h2v ^ SGN, h2v, one2);
                u64 gzq = *(const u64*)(L+LGZ+2*(5*half+q));
                gr[q] = mul2(mul2(gzq,w2p), d);
            }
        }
    }
    __syncwarp();
    // J: GEMM3 (gh1 = ga2 @ W1^T), ga1 = gh1*(1-h1^2) overwrites LH1
    #pragma unroll
    for (int v=0; v<20; v++) acc[v]=0ull;
    #pragma unroll 8
    for (int k=0;k<64;k++){
        u64 wA=pk2(sm[OW1+ s      *65+k]), wB=pk2(sm[OW1+(s+16)*65+k]);
        u64 wC=pk2(sm[OW1+(s+32)*65+k]),   wD=pk2(sm[OW1+(s+48)*65+k]);
        const u64* ap=(const u64*)(L+LGT+k*20) + 5*half;
        #pragma unroll
        for (int q=0;q<5;q++){ u64 av=ap[q];
            fma2(acc[q],wA,av); fma2(acc[5+q],wB,av);
            fma2(acc[10+q],wC,av); fma2(acc[15+q],wD,av); }
    }
    {
        const u64 SGN = 0x8000000080000000ULL;
        u64 one2 = pk2(1.0f);
        #pragma unroll
        for (int i=0;i<4;i++){
            u64* hr=(u64*)(L+LH1+(s+16*i)*20) + 5*half;
            #pragma unroll
            for (int q=0;q<5;q++){
                u64 h1v=hr[q];
                u64 d = fma2o(h1v ^ SGN, h1v, one2);
                hr[q] = mul2(acc[i*5+q], d);
            }
        }
    }
    __syncwarp();
    // K: GEMM4 gfeat[n][i] = sum_k ga1[k][n] W0[i][k]  (LGF over dead LGT)
    if (s < 15){
        u64 a4[5];
        #pragma unroll
        for (int q=0;q<5;q++) a4[q]=0ull;
        #pragma unroll 8
        for (int k=0;k<64;k++){
            u64 w=pk2(sm[OW0+s*65+k]);
            const u64* ap=(const u64*)(L+LH1+k*20) + 5*half;
            #pragma unroll
            for (int q=0;q<5;q++) fma2(a4[q],w,ap[q]);
        }
        #pragma unroll
        for (int q=0;q<5;q++){
            float lo,hi; upk(a4[q],lo,hi);
            int n0 = 10*half + 2*q;
            L[LGF+n0*16+s]=lo; L[LGF+(n0+1)*16+s]=hi;
        }
    }
    __syncwarp();
    // L: force, gO (aliases dead LFCR), torque
    if (t < 3){
        float f=0.f; const float* O=L+LSO;
        for (int n=0;n<NN;n++){
            const float* g=L+LGF+n*16; const float* NO=L+LNOR+n*9;
            f += g[0]*O[t*3]+g[1]*O[t*3+1]+g[2]*O[t*3+2];
            f += g[3]*NO[t*3]+g[4]*NO[t*3+1]+g[5]*NO[t*3+2];
        }
        if (wr) out[(size_t)batch*3+t]=f;
    }
    if (t >= 4 && t < 13){
        int a=(t-4)/3, bb=(t-4)%3; float g2=0.f;
        for (int n=0;n<NN;n++){
            const float* g=L+LGF+n*16; const float* NO=L+LNOR+n*9;
            g2 += L[LNDN+n*3+a]*g[bb];
            g2 += g[6+3*bb+0]*NO[a*3+0]+g[6+3*bb+1]*NO[a*3+1]+g[6+3*bb+2]*NO[a*3+2];
        }
        L[LGO+a*3+bb]=g2;
    }
    __syncwarp();
    if (t==0 && wr){
        const float* gO=L+LGO; const float* O=L+LSO;
        float tx=0.f,ty=0.f,tz=0.f;
        #pragma unroll
        for (int c=0;c<3;c++){
            float u0=gO[c],u1=gO[3+c],u2=gO[6+c];
            float v0=O[c], v1=O[3+c], v2=O[6+c];
            tx += u1*v2-u2*v1; ty += u2*v0-u0*v2; tz += u0*v1-u1*v0;
        }
        out[(size_t)3*B+(size_t)batch*3+0]=tx;
        out[(size_t)3*B+(size_t)batch*3+1]=ty;
        out[(size_t)3*B+(size_t)batch*3+2]=tz;
    }
}

extern "C" void kernel_launch(void* const* d_in, const int* in_sizes, int n_in,
                              void* d_out, int out_size) {
    const float* dr  = (const float*)d_in[0];
    const float* ori = (const float*)d_in[1];
    const float* nor = (const float*)d_in[2];
    const float* W0  = (const float*)d_in[3];
    const float* b0  = (const float*)d_in[4];
    const float* W1  = (const float*)d_in[5];
    const float* b1  = (const float*)d_in[6];
    const float* W2  = (const float*)d_in[7];
    const float* b2  = (const float*)d_in[8];
    const float* f1  = (const float*)d_in[9];
    const float* f2  = (const float*)d_in[10];
    float* out = (float*)d_out;

    int B = in_sizes[0] / (NBC * 3);
    int blocks = (B + LPB - 1) / LPB;
    size_t shmem = (size_t)SMEM_FLOATS * sizeof(float);
    cudaFuncSetAttribute(ep_kernel, cudaFuncAttributeMaxDynamicSharedMemorySize, (int)shmem);
    ep_kernel<<<blocks, TPB, shmem>>>(dr, ori, nor, W0, b0, W1, b1, W2, b2, f1, f2, out, B);
}